// round 4
// baseline (speedup 1.0000x reference)
#include <cuda_runtime.h>
#include <stdint.h>
#include <math.h>

#define MAXN    131072
#define KTOP    4096
#define MAXDET  100
#define THRESH  0.5f
#define NMSTHR  0.5f

typedef unsigned long long u64;
typedef unsigned int u32;

// ---------------- static device scratch ----------------
__device__ float              g_score[MAXN];
__device__ u32                g_key[MAXN];
__device__ float4             g_box[MAXN];
__device__ int                g_cls[MAXN];
__device__ __align__(16) int  g_hist1[65536];
__device__ __align__(16) int  g_hist2[65536];
__device__ __align__(16) int  g_coarse1[1024];
__device__ __align__(16) int  g_coarse2[1024];
__device__ int                g_cnt[4];        // [0]=cnt_gt, [1]=cnt_eq
__device__ int                g_selinfo[2];    // [0]=bucket B1, [1]=count above B1
__device__ u32                g_Tkey;
__device__ int                g_G;
__device__ u64                g_sel[KTOP];     // composite (key<<32)|~idx  (UNSORTED)
__device__ int                g_eq[KTOP];

__device__ __forceinline__ u32 fkey(float f) {
    u32 u = __float_as_uint(f);
    return u ^ ((u >> 31) ? 0xFFFFFFFFu : 0x80000000u);
}

// ---------------- kernel 1: warp-per-anchor argmax + decode + 2-level histogram ----------------
__global__ void k_prep(const float* __restrict__ reg, const float* __restrict__ cls,
                       const float* __restrict__ anc, int N, int C, float Wm1, float Hm1) {
    int gid = blockIdx.x * blockDim.x + threadIdx.x;
    // zero scratch consumed later THIS replay (kernel-boundary ordered)
    if (gid < 65536) g_hist2[gid] = 0;
    if (gid < 1024)  g_coarse2[gid] = 0;
    if (gid < 4)     g_cnt[gid] = 0;

    int gw = gid >> 5;
    int lane = threadIdx.x & 31;
    if (gw >= N) return;
    int i = gw;

    const float* row = cls + (size_t)i * C;
    float best = -1e30f; int bc = 0x7FFFFFFF;
    for (int k = lane; k < C; k += 32) {
        float v = row[k];
        if (v > best) { best = v; bc = k; }       // ascending k => first occurrence
    }
#pragma unroll
    for (int off = 16; off; off >>= 1) {
        float ov = __shfl_down_sync(0xFFFFFFFFu, best, off);
        int   oi = __shfl_down_sync(0xFFFFFFFFu, bc, off);
        if (ov > best || (ov == best && oi < bc)) { best = ov; bc = oi; }
    }

    if (lane == 0) {
        float4 a = reinterpret_cast<const float4*>(anc)[i];
        float4 r = reinterpret_cast<const float4*>(reg)[i];
        float ya = (a.x + a.z) * 0.5f, xa = (a.y + a.w) * 0.5f;
        float ha = a.z - a.x, wa = a.w - a.y;
        float w = expf(r.w) * wa, h = expf(r.z) * ha;
        float yc = r.x * ha + ya, xc = r.y * wa + xa;
        float x1 = fmaxf(xc - w * 0.5f, 0.0f);
        float y1 = fmaxf(yc - h * 0.5f, 0.0f);
        float x2 = fminf(xc + w * 0.5f, Wm1);
        float y2 = fminf(yc + h * 0.5f, Hm1);
        g_box[i] = make_float4(x1, y1, x2, y2);

        float cand = (best > THRESH) ? best : -1.0f;
        g_score[i] = cand;
        g_cls[i] = bc;
        u32 k = fkey(cand);
        g_key[i] = k;
        atomicAdd(&g_hist1[k >> 16], 1);
        atomicAdd(&g_coarse1[k >> 22], 1);
    }
}

// ---------------- block-local radix-level find (blockDim == 256) ----------------
struct FindShared { int suf[257]; int binres[2]; int h[64]; int hs[65]; int res[2]; };

__device__ void find_level(const int* __restrict__ coarse, const int* __restrict__ hist,
                           int base, FindShared& S, int& bucket, int& cntAbove) {
    int t = threadIdx.x;
    int4 cv = reinterpret_cast<const int4*>(coarse)[t];
    int seg = cv.x + cv.y + cv.z + cv.w;
    S.suf[t] = seg;
    __syncthreads();
#pragma unroll
    for (int off = 1; off < 256; off <<= 1) {
        int v = (t + off < 256) ? S.suf[t + off] : 0;
        __syncthreads();
        S.suf[t] += v;
        __syncthreads();
    }
    int exc = (t < 255) ? S.suf[t + 1] : 0;       // keys strictly above my segment
    int cg = exc + base;
    if (cg < KTOP && cg + seg >= KTOP) {          // unique crossing segment
        int vals[4] = { cv.w, cv.z, cv.y, cv.x }; // bins 4t+3 .. 4t (high->low)
        int acc = cg;
#pragma unroll
        for (int j = 0; j < 4; j++) {
            int hh = vals[j];
            if (acc + hh >= KTOP) { S.binres[0] = 4 * t + (3 - j); S.binres[1] = acc; break; }
            acc += hh;
        }
    }
    __syncthreads();
    int bin = S.binres[0], bb = S.binres[1];
    if (t < 64) { S.h[t] = hist[bin * 64 + t]; S.hs[t] = S.h[t]; }
    __syncthreads();
#pragma unroll
    for (int off = 1; off < 64; off <<= 1) {
        int v = 0;
        if (t < 64) v = (t + off < 64) ? S.hs[t + off] : 0;
        __syncthreads();
        if (t < 64) S.hs[t] += v;
        __syncthreads();
    }
    if (t < 64) {
        int exc2 = (t < 63) ? S.hs[t + 1] : 0;
        int cg2 = exc2 + bb;
        if (cg2 < KTOP && cg2 + S.h[t] >= KTOP) { S.res[0] = bin * 64 + t; S.res[1] = cg2; }
    }
    __syncthreads();
    bucket = S.res[0];
    cntAbove = S.res[1];
}

// ---------------- kernel 2: find level-1 (preamble) + level-2 histogram ----------------
__global__ void k_hist2(int N) {
    __shared__ FindShared FS;
    int B1, base1;
    find_level(g_coarse1, g_hist1, 0, FS, B1, base1);
    if (threadIdx.x == 0) { g_selinfo[0] = B1; g_selinfo[1] = base1; }  // identical from all blocks
    int i = blockIdx.x * 256 + threadIdx.x;
    if (i >= N) return;
    u32 k = g_key[i];
    if ((int)(k >> 16) == B1) {
        atomicAdd(&g_hist2[k & 0xFFFFu], 1);
        atomicAdd(&g_coarse2[(k & 0xFFFFu) >> 6], 1);
    }
}

// ---------------- kernel 3: find level-2 (preamble) + compaction ----------------
__global__ void k_compact(int N) {
    __shared__ FindShared FS;
    int base1 = g_selinfo[1];
    int B2, G;
    find_level(g_coarse2, g_hist2, base1, FS, B2, G);
    u32 T = ((u32)g_selinfo[0] << 16) | (u32)B2;
    if (blockIdx.x == 0 && threadIdx.x == 0) { g_Tkey = T; g_G = G; }
    int i = blockIdx.x * 256 + threadIdx.x;
    if (i < 65536) g_hist1[i] = 0;    // reset for next replay
    if (i < 1024)  g_coarse1[i] = 0;
    if (i >= N) return;
    u32 k = g_key[i];
    if (k > T) {
        int p = atomicAdd(&g_cnt[0], 1);
        g_sel[p] = ((u64)k << 32) | (u32)(~(u32)i);
    } else if (k == T) {
        int p = atomicAdd(&g_cnt[1], 1);
        if (p < KTOP) g_eq[p] = i;
    }
}

// ---------------- kernel 4: fill_eq + sort-free greedy NMS + output (1 block, 1024 thr) ----------------
__global__ void k_nms(float* __restrict__ out, int out_size) {
    extern __shared__ float4 sbox[];              // KTOP boxes, 64 KB dynamic
    __shared__ u64 s_wm[32];
    __shared__ u64 s_M;
    __shared__ float4 s_selbox;
    __shared__ int s_keep[MAXDET];
    __shared__ int s_red[32];
    int t = threadIdx.x;

    // ---- fill equal-key slots (lowest anchor indices first) ----
    int G = g_G;
    int need = KTOP - G;
    int E = g_cnt[1]; if (E > KTOP) E = KTOP;
    u32 T = g_Tkey;
    for (int r = 0; r < need; r++) {
        int m = 0x7FFFFFFF;
        for (int j = t; j < E; j += 1024) m = min(m, g_eq[j]);
#pragma unroll
        for (int off = 16; off; off >>= 1) m = min(m, __shfl_xor_sync(0xFFFFFFFFu, m, off));
        if ((t & 31) == 0) s_red[t >> 5] = m;
        __syncthreads();
        if (t < 32) {
            int v = s_red[t];
#pragma unroll
            for (int off = 16; off; off >>= 1) v = min(v, __shfl_xor_sync(0xFFFFFFFFu, v, off));
            if (t == 0) s_red[0] = v;
        }
        __syncthreads();
        int minv = s_red[0];
        for (int j = t; j < E; j += 1024) if (g_eq[j] == minv) g_eq[j] = 0x7FFFFFFF;
        if (t == 0) g_sel[G + r] = ((u64)T << 32) | (u32)(~(u32)minv);
        __syncthreads();
    }

    // ---- load candidates: 4 per thread, boxes to regs + smem ----
    const u64 VT = (((u64)fkey(THRESH)) << 32) | 0xFFFFFFFFull;  // valid <=> comp > VT
    u64 comp[4]; float4 bx[4]; float area[4]; bool alive[4];
#pragma unroll
    for (int c = 0; c < 4; c++) {
        int slot = c * 1024 + t;
        u64 v = g_sel[slot];
        comp[c] = v;
        int idx = (int)(~(u32)v);
        float4 b = g_box[idx];
        bx[c] = b;
        sbox[slot] = b;
        area[c] = fmaxf(b.z - b.x, 0.0f) * fmaxf(b.w - b.y, 0.0f);
        alive[c] = v > VT;
    }
    __syncthreads();

    // ---- greedy NMS: pick max alive composite each round ----
    int cnt = 0;
    while (true) {
        u64 my = 0;
#pragma unroll
        for (int c = 0; c < 4; c++) if (alive[c] && comp[c] > my) my = comp[c];
#pragma unroll
        for (int off = 16; off; off >>= 1) {
            u64 o = __shfl_xor_sync(0xFFFFFFFFu, my, off);
            if (o > my) my = o;
        }
        if ((t & 31) == 0) s_wm[t >> 5] = my;
        __syncthreads();
        if (t < 32) {
            u64 v = s_wm[t];
#pragma unroll
            for (int off = 16; off; off >>= 1) {
                u64 o = __shfl_xor_sync(0xFFFFFFFFu, v, off);
                if (o > v) v = o;
            }
            if (t == 0) s_M = v;
        }
        __syncthreads();
        u64 M = s_M;
        if (M == 0) break;
#pragma unroll
        for (int c = 0; c < 4; c++) {
            if (alive[c] && comp[c] == M) { alive[c] = false; s_selbox = bx[c]; }
        }
        if (t == 0) s_keep[cnt] = (int)(~(u32)M);
        cnt++;
        __syncthreads();
        if (cnt >= MAXDET) break;   // num_det caps at MAXDET; only first MAXDET kept are output
        float4 bj = s_selbox;
        float areaj = fmaxf(bj.z - bj.x, 0.0f) * fmaxf(bj.w - bj.y, 0.0f);
#pragma unroll
        for (int c = 0; c < 4; c++) {
            if (alive[c]) {
                float ix1 = fmaxf(bx[c].x, bj.x), iy1 = fmaxf(bx[c].y, bj.y);
                float ix2 = fminf(bx[c].z, bj.z), iy2 = fminf(bx[c].w, bj.w);
                float inter = fmaxf(ix2 - ix1, 0.0f) * fmaxf(iy2 - iy1, 0.0f);
                float uni = area[c] + areaj - inter;
                float iou = inter / fmaxf(uni, 1e-8f);
                if (iou > NMSTHR) alive[c] = false;
            }
        }
    }
    __syncthreads();

    // ---- output ----
    for (int k = t; k < out_size; k += 1024) out[k] = 0.0f;
    __syncthreads();
    int nw = min(cnt, MAXDET);
    if (t < nw) {
        int idx = s_keep[t];
        float4 b = g_box[idx];
        out[t * 4 + 0] = b.x;
        out[t * 4 + 1] = b.y;
        out[t * 4 + 2] = b.z;
        out[t * 4 + 3] = b.w;
        out[4 * MAXDET + t] = g_score[idx];
        out[5 * MAXDET + t] = (float)g_cls[idx];
    }
    if (t == 0 && out_size > 6 * MAXDET) out[6 * MAXDET] = (float)nw;
}

// ---------------- launcher ----------------
extern "C" void kernel_launch(void* const* d_in, const int* in_sizes, int n_in,
                              void* d_out, int out_size) {
    const float* reg = (const float*)d_in[1];
    const float* cls = (const float*)d_in[2];
    const float* anc = (const float*)d_in[3];
    int N = in_sizes[1] / 4;
    int C = (int)((long long)in_sizes[2] / N);
    int HW = in_sizes[0] / 3;
    int side = (int)(sqrt((double)HW) + 0.5);
    float Wm1 = (float)(side - 1);
    float Hm1 = (float)(side - 1);

    static int smem_set = 0;
    if (!smem_set) {
        cudaFuncSetAttribute(k_nms, cudaFuncAttributeMaxDynamicSharedMemorySize,
                             KTOP * (int)sizeof(float4));
        smem_set = 1;
    }

    int prep_blocks = (N * 32 + 255) / 256;
    int pass_blocks = (N + 255) / 256;

    k_prep<<<prep_blocks, 256>>>(reg, cls, anc, N, C, Wm1, Hm1);
    k_hist2<<<pass_blocks, 256>>>(N);
    k_compact<<<pass_blocks, 256>>>(N);
    k_nms<<<1, 1024, KTOP * sizeof(float4)>>>((float*)d_out, out_size);
}

// round 5
// speedup vs baseline: 1.9219x; 1.9219x over previous
#include <cuda_runtime.h>
#include <stdint.h>
#include <math.h>

#define MAXN    131072
#define KTOP    4096
#define MAXDET  100
#define THRESH  0.5f
#define NMSTHR  0.5f

typedef unsigned long long u64;
typedef unsigned int u32;

// ---------------- static device scratch ----------------
__device__ float              g_score[MAXN];
__device__ u32                g_key[MAXN];
__device__ float4             g_box[MAXN];
__device__ int                g_cls[MAXN];
__device__ __align__(16) int  g_hist1[65536];   // zeroed by k_hist2 (after consumption in k_prep last block)
__device__ __align__(16) int  g_hist2[65536];   // zeroed by k_compact
__device__ __align__(16) int  g_coarse1[1024];
__device__ __align__(16) int  g_coarse2[1024];
__device__ int                g_cnt[4];         // [0]=cnt_gt, [1]=cnt_eq  (zeroed by k_prep)
__device__ int                g_tick[4];        // ticket counters, self-reset by consumer
__device__ int                g_selinfo[2];     // [0]=bucket B1, [1]=count above B1
__device__ u32                g_Tkey;
__device__ int                g_G;
__device__ u64                g_sel[KTOP];      // composite (key<<32)|~idx (unsorted)
__device__ int                g_eq[KTOP];
__device__ float4             g_cbox[KTOP];
__device__ float              g_cscore[KTOP];
__device__ int                g_ccls[KTOP];
__device__ u64                g_mask[(size_t)KTOP * 64];

__device__ __forceinline__ u32 fkey(float f) {
    u32 u = __float_as_uint(f);
    return u ^ ((u >> 31) ? 0xFFFFFFFFu : 0x80000000u);
}
__device__ __forceinline__ float unfkey(u32 k) {
    u32 u = (k & 0x80000000u) ? (k ^ 0x80000000u) : ~k;
    return __uint_as_float(u);
}

// ------- block-wide radix find for 1024 threads (all threads must enter) -------
struct FindShared { int suf[1025]; int binres[2]; int h[64]; int hs[65]; int res[2]; };

__device__ void find_level1024(const int* __restrict__ coarse, const int* __restrict__ hist,
                               int base, FindShared& S, int& bucket, int& cntAbove) {
    int t = threadIdx.x;
    int seg = coarse[t];                    // 1024 bins, one per thread
    S.suf[t] = seg;
    __syncthreads();
    for (int off = 1; off < 1024; off <<= 1) {
        int v = (t + off < 1024) ? S.suf[t + off] : 0;
        __syncthreads();
        S.suf[t] += v;
        __syncthreads();
    }
    int exc = (t < 1023) ? S.suf[t + 1] : 0;   // strictly above my bin
    int cg = exc + base;
    if (cg < KTOP && cg + seg >= KTOP) { S.binres[0] = t; S.binres[1] = cg; }
    __syncthreads();
    int bin = S.binres[0], bb = S.binres[1];
    if (t < 64) { int h = hist[bin * 64 + t]; S.h[t] = h; S.hs[t] = h; }
    __syncthreads();
    for (int off = 1; off < 64; off <<= 1) {
        int v = 0;
        if (t < 64) v = (t + off < 64) ? S.hs[t + off] : 0;
        __syncthreads();
        if (t < 64) S.hs[t] += v;
        __syncthreads();
    }
    if (t < 64) {
        int exc2 = (t < 63) ? S.hs[t + 1] : 0;
        int cg2 = exc2 + bb;
        if (cg2 < KTOP && cg2 + S.h[t] >= KTOP) { S.res[0] = bin * 64 + t; S.res[1] = cg2; }
    }
    __syncthreads();
    bucket = S.res[0];
    cntAbove = S.res[1];
}

// ---------------- kernel 1: argmax+decode+aggregated hist; last block finds B1 ----------------
__global__ __launch_bounds__(1024) void k_prep(const float* __restrict__ reg,
        const float* __restrict__ cls, const float* __restrict__ anc,
        int N, int C, float Wm1, float Hm1, int nblocks) {
    __shared__ u32 s_bucket[32];
    __shared__ FindShared FS;
    __shared__ int s_last;
    int tid = threadIdx.x;
    int gid = blockIdx.x * 1024 + tid;
    if (gid < 65536) g_hist2[gid] = 0;
    if (gid < 1024)  g_coarse2[gid] = 0;
    if (gid < 4)     g_cnt[gid] = 0;

    int gw = gid >> 5;          // anchor id
    int lane = tid & 31;
    int warp = tid >> 5;
    u32 bucket = 0xFFFFFFFFu;

    if (gw < N) {
        const float* row = cls + (size_t)gw * C;
        float bestv = -1e30f; int bc = 0x7FFFFFFF;
        for (int k = lane; k < C; k += 32) {
            float v = row[k];
            if (v > bestv) { bestv = v; bc = k; }   // ascending => first occurrence per lane
        }
        u32 mk = fkey(bestv);
        u32 m = __reduce_max_sync(0xFFFFFFFFu, mk);
        u32 cbc = (mk == m) ? (u32)bc : 0xFFFFFFFFu;
        u32 mbc = __reduce_min_sync(0xFFFFFFFFu, cbc);   // global first occurrence
        if (lane == 0) {
            float best = unfkey(m);
            float4 a = reinterpret_cast<const float4*>(anc)[gw];
            float4 r = reinterpret_cast<const float4*>(reg)[gw];
            float ya = (a.x + a.z) * 0.5f, xa = (a.y + a.w) * 0.5f;
            float ha = a.z - a.x, wa = a.w - a.y;
            float w = expf(r.w) * wa, h = expf(r.z) * ha;
            float yc = r.x * ha + ya, xc = r.y * wa + xa;
            g_box[gw] = make_float4(fmaxf(xc - w * 0.5f, 0.0f), fmaxf(yc - h * 0.5f, 0.0f),
                                    fminf(xc + w * 0.5f, Wm1),  fminf(yc + h * 0.5f, Hm1));
            float cand = (best > THRESH) ? best : -1.0f;
            g_score[gw] = cand;
            g_cls[gw] = (int)mbc;
            u32 k = fkey(cand);
            g_key[gw] = k;
            bucket = k >> 16;
        }
    }
    if (lane == 0) s_bucket[warp] = bucket;
    __syncthreads();
    // warp 0 aggregates the block's 32 bucket ids -> few global atomics
    if (tid < 32) {
        u32 b = s_bucket[tid];
        bool v = (b != 0xFFFFFFFFu);
        u32 mm = __match_any_sync(0xFFFFFFFFu, b);
        if (v && tid == (__ffs(mm) - 1)) atomicAdd(&g_hist1[b], __popc(mm));
        u32 cb = b >> 6;
        u32 m2 = __match_any_sync(0xFFFFFFFFu, cb);
        if (v && tid == (__ffs(m2) - 1)) atomicAdd(&g_coarse1[cb], __popc(m2));
    }
    // last-block: find level-1 bucket
    __threadfence();
    if (tid == 0) s_last = atomicAdd(&g_tick[0], 1);
    __syncthreads();
    if (s_last == nblocks - 1) {
        int B1, base1;
        find_level1024(g_coarse1, g_hist1, 0, FS, B1, base1);
        if (tid == 0) { g_selinfo[0] = B1; g_selinfo[1] = base1; g_tick[0] = 0; }
    }
}

// ---------------- kernel 2: level-2 histogram; last block finds Tkey/G ----------------
__global__ __launch_bounds__(1024) void k_hist2(int N, int nblocks) {
    __shared__ FindShared FS;
    __shared__ int s_last;
    int tid = threadIdx.x;
    int i = blockIdx.x * 1024 + tid;
    if (i < 65536) g_hist1[i] = 0;       // consumed in k_prep's last block; reset for next replay
    if (i < 1024)  g_coarse1[i] = 0;
    int B1 = g_selinfo[0];
    if (i < N) {
        u32 k = g_key[i];
        if ((int)(k >> 16) == B1) {
            atomicAdd(&g_hist2[k & 0xFFFFu], 1);
            atomicAdd(&g_coarse2[(k & 0xFFFFu) >> 6], 1);
        }
    }
    __threadfence();
    if (tid == 0) s_last = atomicAdd(&g_tick[1], 1);
    __syncthreads();
    if (s_last == nblocks - 1) {
        int B2, G;
        find_level1024(g_coarse2, g_hist2, g_selinfo[1], FS, B2, G);
        if (tid == 0) {
            g_Tkey = ((u32)g_selinfo[0] << 16) | (u32)B2;
            g_G = G;
            g_tick[1] = 0;
        }
    }
}

// ---------------- kernel 3: compaction; last block fills equal-key slots ----------------
__global__ __launch_bounds__(1024) void k_compact(int N, int nblocks) {
    __shared__ int s_last;
    __shared__ int s_red[32];
    int tid = threadIdx.x;
    int i = blockIdx.x * 1024 + tid;
    if (i < 65536) g_hist2[i] = 0;       // consumed in k_hist2's last block
    if (i < 1024)  g_coarse2[i] = 0;
    u32 T = g_Tkey;
    if (i < N) {
        u32 k = g_key[i];
        if (k > T) {
            int p = atomicAdd(&g_cnt[0], 1);
            g_sel[p] = ((u64)k << 32) | (u32)(~(u32)i);
        } else if (k == T) {
            int p = atomicAdd(&g_cnt[1], 1);
            if (p < KTOP) g_eq[p] = i;
        }
    }
    __threadfence();
    if (tid == 0) s_last = atomicAdd(&g_tick[2], 1);
    __syncthreads();
    if (s_last == nblocks - 1) {
        // fill slots [G, KTOP) with equal-key candidates, lowest anchor index first
        int G = g_G;
        int need = KTOP - G;
        int E = g_cnt[1]; if (E > KTOP) E = KTOP;
        for (int r = 0; r < need; r++) {
            int m = 0x7FFFFFFF;
            for (int j = tid; j < E; j += 1024) m = min(m, g_eq[j]);
#pragma unroll
            for (int off = 16; off; off >>= 1) m = min(m, __shfl_xor_sync(0xFFFFFFFFu, m, off));
            if ((tid & 31) == 0) s_red[tid >> 5] = m;
            __syncthreads();
            if (tid < 32) {
                int v = s_red[tid];
#pragma unroll
                for (int off = 16; off; off >>= 1) v = min(v, __shfl_xor_sync(0xFFFFFFFFu, v, off));
                if (tid == 0) s_red[0] = v;
            }
            __syncthreads();
            int minv = s_red[0];
            for (int j = tid; j < E; j += 1024) if (g_eq[j] == minv) g_eq[j] = 0x7FFFFFFF;
            if (tid == 0) g_sel[G + r] = ((u64)T << 32) | (u32)(~(u32)minv);
            __syncthreads();
        }
        if (tid == 0) g_tick[2] = 0;
    }
}

// ---------------- kernel 4: rank-by-count sort + gather (64 blocks x 256) ----------------
__global__ __launch_bounds__(256) void k_rank() {
    __shared__ u64 s[4][1025];               // padded: conflict-free cross-segment reads
    int t = threadIdx.x;
    for (int j = t; j < KTOP; j += 256) s[j >> 10][j & 1023] = g_sel[j];
    __syncthreads();
    int cand = blockIdx.x * 64 + (t >> 2);
    int seg = t & 3;
    u64 my = g_sel[cand];
    const u64* p = s[seg];
    int r = 0;
#pragma unroll 8
    for (int j = 0; j < 1024; j++) r += (p[j] > my);
    r += __shfl_down_sync(0xFFFFFFFFu, r, 2, 4);
    r += __shfl_down_sync(0xFFFFFFFFu, r, 1, 4);
    if (seg == 0) {
        int idx = (int)(~(u32)my);
        g_cbox[r] = g_box[idx];
        g_cscore[r] = g_score[idx];
        g_ccls[r] = g_cls[idx];
    }
}

// ---------------- kernel 5: NMS suppression bitmask (4096x4096) ----------------
__global__ __launch_bounds__(256) void k_mask() {
    __shared__ float4 cb[64];
    int t = threadIdx.x;
    int col0 = blockIdx.x * 64;
    int i = blockIdx.y * 256 + t;
    if (t < 64) cb[t] = g_cbox[col0 + t];
    __syncthreads();
    float4 bi = g_cbox[i];
    float areai = fmaxf(bi.z - bi.x, 0.0f) * fmaxf(bi.w - bi.y, 0.0f);
    u64 bits = 0;
#pragma unroll 4
    for (int c = 0; c < 64; c++) {
        int j = col0 + c;
        if (j > i) {
            float4 bj = cb[c];
            float ix1 = fmaxf(bi.x, bj.x), iy1 = fmaxf(bi.y, bj.y);
            float ix2 = fminf(bi.z, bj.z), iy2 = fminf(bi.w, bj.w);
            float inter = fmaxf(ix2 - ix1, 0.0f) * fmaxf(iy2 - iy1, 0.0f);
            float areaj = fmaxf(bj.z - bj.x, 0.0f) * fmaxf(bj.w - bj.y, 0.0f);
            float uni = areai + areaj - inter;
            float iou = inter / fmaxf(uni, 1e-8f);
            if (iou > NMSTHR) bits |= 1ull << c;
        }
    }
    g_mask[(size_t)i * 64 + blockIdx.x] = bits;
}

// ---------------- kernel 6: 1-warp greedy scan (register bitmap) + output ----------------
__global__ void k_scan(float* __restrict__ out, int out_size) {
    int lane = threadIdx.x;
    __shared__ int keep[MAXDET];
    u64 r0 = 0, r1 = 0;
    int w0 = lane, w1 = lane + 32;
    for (int b = 0; b < 64; b++) {
        if (g_cscore[w0 * 64 + b] <= THRESH) r0 |= 1ull << b;
        if (g_cscore[w1 * 64 + b] <= THRESH) r1 |= 1ull << b;
    }
    int cnt = 0;
    while (true) {
        u64 m0 = ~r0, m1 = ~r1;
        int c0 = m0 ? (w0 * 64 + (__ffsll((long long)m0) - 1)) : 0x7FFFFFFF;
        int c1 = m1 ? (w1 * 64 + (__ffsll((long long)m1) - 1)) : 0x7FFFFFFF;
        int c = min(c0, c1);
#pragma unroll
        for (int off = 16; off; off >>= 1) c = min(c, __shfl_xor_sync(0xFFFFFFFFu, c, off));
        if (c == 0x7FFFFFFF) break;
        if (lane == 0) keep[cnt] = c;
        cnt++;
        if (cnt >= MAXDET) break;
        r0 |= g_mask[(size_t)c * 64 + lane];
        r1 |= g_mask[(size_t)c * 64 + 32 + lane];
        int w = c >> 6;
        u64 sb = 1ull << (c & 63);
        if (w == w0) r0 |= sb;
        else if (w == w1) r1 |= sb;
    }
    __syncwarp();
    for (int k = lane; k < out_size; k += 32) out[k] = 0.0f;
    __syncwarp();
    int nw = min(cnt, MAXDET);
    for (int s = lane; s < nw; s += 32) {
        int j = keep[s];
        float4 b = g_cbox[j];
        out[s * 4 + 0] = b.x;
        out[s * 4 + 1] = b.y;
        out[s * 4 + 2] = b.z;
        out[s * 4 + 3] = b.w;
        out[4 * MAXDET + s] = g_cscore[j];
        out[5 * MAXDET + s] = (float)g_ccls[j];
    }
    if (lane == 0 && out_size > 6 * MAXDET) out[6 * MAXDET] = (float)nw;
}

// ---------------- launcher ----------------
extern "C" void kernel_launch(void* const* d_in, const int* in_sizes, int n_in,
                              void* d_out, int out_size) {
    const float* reg = (const float*)d_in[1];
    const float* cls = (const float*)d_in[2];
    const float* anc = (const float*)d_in[3];
    int N = in_sizes[1] / 4;
    int C = (int)((long long)in_sizes[2] / N);
    int HW = in_sizes[0] / 3;
    int side = (int)(sqrt((double)HW) + 0.5);
    float Wm1 = (float)(side - 1);
    float Hm1 = (float)(side - 1);

    int prep_blocks = (N * 32 + 1023) / 1024;
    int pass_blocks = (N + 1023) / 1024;

    k_prep<<<prep_blocks, 1024>>>(reg, cls, anc, N, C, Wm1, Hm1, prep_blocks);
    k_hist2<<<pass_blocks, 1024>>>(N, pass_blocks);
    k_compact<<<pass_blocks, 1024>>>(N, pass_blocks);
    k_rank<<<KTOP / 64, 256>>>();
    k_mask<<<dim3(64, 16), 256>>>();
    k_scan<<<1, 32>>>((float*)d_out, out_size);
}

// round 6
// speedup vs baseline: 2.0600x; 1.0719x over previous
#include <cuda_runtime.h>
#include <stdint.h>
#include <math.h>

#define MAXN    131072
#define KTOP    4096
#define MAXDET  100
#define THRESH  0.5f
#define NMSTHR  0.5f

typedef unsigned long long u64;
typedef unsigned int u32;

// ---------------- static device scratch ----------------
__device__ float              g_score[MAXN];
__device__ u32                g_key[MAXN];
__device__ float4             g_box[MAXN];
__device__ int                g_cls[MAXN];
__device__ __align__(16) int  g_hist1[65536];
__device__ __align__(16) int  g_hist2[65536];
__device__ __align__(16) int  g_coarse1[1024];
__device__ __align__(16) int  g_coarse2[1024];
__device__ int                g_cnt[4];         // [0]=cnt_gt [1]=cnt_eq (prep zeroes) [2]=valid count (scan resets)
__device__ int                g_tick[4];
__device__ int                g_selinfo[2];
__device__ u32                g_Tkey;
__device__ int                g_G;
__device__ u64                g_sel[KTOP];
__device__ int                g_eq[KTOP];
__device__ float4             g_cbox[KTOP];
__device__ float              g_cscore[KTOP];
__device__ int                g_ccls[KTOP];
__device__ u64                g_mask[(size_t)KTOP * 64];   // lower-triangle words never written: stay 0

__device__ __forceinline__ u32 fkey(float f) {
    u32 u = __float_as_uint(f);
    return u ^ ((u >> 31) ? 0xFFFFFFFFu : 0x80000000u);
}
__device__ __forceinline__ float unfkey(u32 k) {
    u32 u = (k & 0x80000000u) ? (k ^ 0x80000000u) : ~k;
    return __uint_as_float(u);
}

// ------- block-wide radix find for 1024 threads -------
struct FindShared { int suf[1025]; int binres[2]; int h[64]; int hs[65]; int res[2]; };

__device__ void find_level1024(const int* __restrict__ coarse, const int* __restrict__ hist,
                               int base, FindShared& S, int& bucket, int& cntAbove) {
    int t = threadIdx.x;
    int seg = coarse[t];
    S.suf[t] = seg;
    __syncthreads();
    for (int off = 1; off < 1024; off <<= 1) {
        int v = (t + off < 1024) ? S.suf[t + off] : 0;
        __syncthreads();
        S.suf[t] += v;
        __syncthreads();
    }
    int exc = (t < 1023) ? S.suf[t + 1] : 0;
    int cg = exc + base;
    if (cg < KTOP && cg + seg >= KTOP) { S.binres[0] = t; S.binres[1] = cg; }
    __syncthreads();
    int bin = S.binres[0], bb = S.binres[1];
    if (t < 64) { int h = hist[bin * 64 + t]; S.h[t] = h; S.hs[t] = h; }
    __syncthreads();
    for (int off = 1; off < 64; off <<= 1) {
        int v = 0;
        if (t < 64) v = (t + off < 64) ? S.hs[t + off] : 0;
        __syncthreads();
        if (t < 64) S.hs[t] += v;
        __syncthreads();
    }
    if (t < 64) {
        int exc2 = (t < 63) ? S.hs[t + 1] : 0;
        int cg2 = exc2 + bb;
        if (cg2 < KTOP && cg2 + S.h[t] >= KTOP) { S.res[0] = bin * 64 + t; S.res[1] = cg2; }
    }
    __syncthreads();
    bucket = S.res[0];
    cntAbove = S.res[1];
}

// ---------------- kernel 1: argmax+decode+aggregated hist+valid count; last block finds B1 ----------------
__global__ __launch_bounds__(1024) void k_prep(const float* __restrict__ reg,
        const float* __restrict__ cls, const float* __restrict__ anc,
        int N, int C, float Wm1, float Hm1, int nblocks) {
    __shared__ u32 s_bucket[32];
    __shared__ FindShared FS;
    __shared__ int s_last;
    int tid = threadIdx.x;
    int gid = blockIdx.x * 1024 + tid;
    if (gid < 65536) g_hist2[gid] = 0;
    if (gid < 1024)  g_coarse2[gid] = 0;
    if (gid < 2)     g_cnt[gid] = 0;    // [2] is reset by k_scan

    int gw = gid >> 5;
    int lane = tid & 31;
    int warp = tid >> 5;
    u32 packed = 0xFFFFFFFFu;           // sentinel

    if (gw < N) {
        const float* row = cls + (size_t)gw * C;
        float bestv = -1e30f; int bc = 0x7FFFFFFF;
        for (int k = lane; k < C; k += 32) {
            float v = row[k];
            if (v > bestv) { bestv = v; bc = k; }
        }
        u32 mk = fkey(bestv);
        u32 m = __reduce_max_sync(0xFFFFFFFFu, mk);
        u32 cbc = (mk == m) ? (u32)bc : 0xFFFFFFFFu;
        u32 mbc = __reduce_min_sync(0xFFFFFFFFu, cbc);
        if (lane == 0) {
            float best = unfkey(m);
            float4 a = reinterpret_cast<const float4*>(anc)[gw];
            float4 r = reinterpret_cast<const float4*>(reg)[gw];
            float ya = (a.x + a.z) * 0.5f, xa = (a.y + a.w) * 0.5f;
            float ha = a.z - a.x, wa = a.w - a.y;
            float w = expf(r.w) * wa, h = expf(r.z) * ha;
            float yc = r.x * ha + ya, xc = r.y * wa + xa;
            g_box[gw] = make_float4(fmaxf(xc - w * 0.5f, 0.0f), fmaxf(yc - h * 0.5f, 0.0f),
                                    fminf(xc + w * 0.5f, Wm1),  fminf(yc + h * 0.5f, Hm1));
            bool valid = best > THRESH;
            float cand = valid ? best : -1.0f;
            g_score[gw] = cand;
            g_cls[gw] = (int)mbc;
            u32 k = fkey(cand);
            g_key[gw] = k;
            packed = (k >> 16) | (valid ? 0x10000u : 0u);
        }
    }
    if (lane == 0) s_bucket[warp] = packed;
    __syncthreads();
    if (tid < 32) {
        u32 raw = s_bucket[tid];
        bool present = raw != 0xFFFFFFFFu;
        u32 b = raw & 0xFFFFu;
        // valid count: one atomic per block
        u32 vb = __ballot_sync(0xFFFFFFFFu, present && (raw & 0x10000u));
        if (tid == 0 && vb) atomicAdd(&g_cnt[2], __popc(vb));
        // fine histogram
        u32 mv = present ? b : 0xFFFFFFFFu;
        u32 mm = __match_any_sync(0xFFFFFFFFu, mv);
        if (present && tid == (__ffs(mm) - 1)) atomicAdd(&g_hist1[b], __popc(mm));
        // coarse histogram
        u32 mv2 = present ? (b >> 6) : 0xFFFFFFFFu;
        u32 m2 = __match_any_sync(0xFFFFFFFFu, mv2);
        if (present && tid == (__ffs(m2) - 1)) atomicAdd(&g_coarse1[b >> 6], __popc(m2));
    }
    __threadfence();
    if (tid == 0) s_last = atomicAdd(&g_tick[0], 1);
    __syncthreads();
    if (s_last == nblocks - 1) {
        int B1, base1;
        find_level1024(g_coarse1, g_hist1, 0, FS, B1, base1);
        if (tid == 0) { g_selinfo[0] = B1; g_selinfo[1] = base1; g_tick[0] = 0; }
    }
}

// ---------------- kernel 2: level-2 histogram; last block finds Tkey/G ----------------
__global__ __launch_bounds__(1024) void k_hist2(int N, int nblocks) {
    __shared__ FindShared FS;
    __shared__ int s_last;
    int tid = threadIdx.x;
    int i = blockIdx.x * 1024 + tid;
    if (i < 65536) g_hist1[i] = 0;
    if (i < 1024)  g_coarse1[i] = 0;
    int B1 = g_selinfo[0];
    if (i < N) {
        u32 k = g_key[i];
        if ((int)(k >> 16) == B1) {
            atomicAdd(&g_hist2[k & 0xFFFFu], 1);
            atomicAdd(&g_coarse2[(k & 0xFFFFu) >> 6], 1);
        }
    }
    __threadfence();
    if (tid == 0) s_last = atomicAdd(&g_tick[1], 1);
    __syncthreads();
    if (s_last == nblocks - 1) {
        int B2, G;
        find_level1024(g_coarse2, g_hist2, g_selinfo[1], FS, B2, G);
        if (tid == 0) {
            g_Tkey = ((u32)g_selinfo[0] << 16) | (u32)B2;
            g_G = G;
            g_tick[1] = 0;
        }
    }
}

// ---------------- kernel 3: warp-aggregated compaction; last block fills equal-key slots ----------------
__global__ __launch_bounds__(1024) void k_compact(int N, int nblocks) {
    __shared__ int s_last;
    __shared__ int s_red[32];
    int tid = threadIdx.x;
    int lane = tid & 31;
    u32 lt = (1u << lane) - 1u;
    int i = blockIdx.x * 1024 + tid;
    if (i < 65536) g_hist2[i] = 0;
    if (i < 1024)  g_coarse2[i] = 0;
    u32 T = g_Tkey;
    u32 k = (i < N) ? g_key[i] : 0u;
    bool pgt = (i < N) && (k > T);
    bool peq = (i < N) && (k == T);
    u32 mgt = __ballot_sync(0xFFFFFFFFu, pgt);
    if (mgt) {
        int leader = __ffs(mgt) - 1;
        int base = 0;
        if (lane == leader) base = atomicAdd(&g_cnt[0], __popc(mgt));
        base = __shfl_sync(0xFFFFFFFFu, base, leader);
        if (pgt) g_sel[base + __popc(mgt & lt)] = ((u64)k << 32) | (u32)(~(u32)i);
    }
    u32 meq = __ballot_sync(0xFFFFFFFFu, peq);
    if (meq) {
        int leader = __ffs(meq) - 1;
        int base = 0;
        if (lane == leader) base = atomicAdd(&g_cnt[1], __popc(meq));
        base = __shfl_sync(0xFFFFFFFFu, base, leader);
        if (peq) {
            int p = base + __popc(meq & lt);
            if (p < KTOP) g_eq[p] = i;
        }
    }
    __threadfence();
    if (tid == 0) s_last = atomicAdd(&g_tick[2], 1);
    __syncthreads();
    if (s_last == nblocks - 1) {
        int G = g_G;
        int need = KTOP - G;
        int E = g_cnt[1]; if (E > KTOP) E = KTOP;
        for (int r = 0; r < need; r++) {
            int m = 0x7FFFFFFF;
            for (int j = tid; j < E; j += 1024) m = min(m, g_eq[j]);
            m = (int)__reduce_min_sync(0xFFFFFFFFu, (u32)m);
            if (lane == 0) s_red[tid >> 5] = m;
            __syncthreads();
            if (tid < 32) {
                int v = (int)__reduce_min_sync(0xFFFFFFFFu, (u32)s_red[tid]);
                if (tid == 0) s_red[0] = v;
            }
            __syncthreads();
            int minv = s_red[0];
            for (int j = tid; j < E; j += 1024) if (g_eq[j] == minv) g_eq[j] = 0x7FFFFFFF;
            if (tid == 0) g_sel[G + r] = ((u64)T << 32) | (u32)(~(u32)minv);
            __syncthreads();
        }
        if (tid == 0) g_tick[2] = 0;
    }
}

// ---------------- kernel 4: rank-by-count sort + gather (256 blocks x 256) ----------------
__global__ __launch_bounds__(256) void k_rank() {
    __shared__ u64 s[KTOP + 16];                 // pad 1 u64 per 256 entries
    int t = threadIdx.x;
    for (int j = t; j < KTOP; j += 256) s[j + (j >> 8)] = g_sel[j];
    __syncthreads();
    int local = t >> 4;                          // 0..15
    int seg = t & 15;
    int cand = blockIdx.x * 16 + local;
    u64 my = s[cand + (cand >> 8)];
    const u64* p = s + seg * 256 + seg;          // contiguous, pad-offset folded in
    int r = 0;
#pragma unroll 16
    for (int j = 0; j < 256; j++) r += (p[j] > my);
#pragma unroll
    for (int off = 8; off; off >>= 1) r += __shfl_down_sync(0xFFFFFFFFu, r, off, 16);
    if (seg == 0) {
        int idx = (int)(~(u32)my);
        g_cbox[r] = g_box[idx];
        g_cscore[r] = g_score[idx];
        g_ccls[r] = g_cls[idx];
    }
}

// ---------------- kernel 5: NMS bitmask, upper-triangle blocks only ----------------
__global__ __launch_bounds__(256) void k_mask() {
    if (blockIdx.x < 4 * blockIdx.y) return;     // those words are provably always zero
    __shared__ float4 cb[64];
    int t = threadIdx.x;
    int col0 = blockIdx.x * 64;
    int i = blockIdx.y * 256 + t;
    if (t < 64) cb[t] = g_cbox[col0 + t];
    __syncthreads();
    float4 bi = g_cbox[i];
    float areai = fmaxf(bi.z - bi.x, 0.0f) * fmaxf(bi.w - bi.y, 0.0f);
    u64 bits = 0;
#pragma unroll 4
    for (int c = 0; c < 64; c++) {
        int j = col0 + c;
        if (j > i) {
            float4 bj = cb[c];
            float ix1 = fmaxf(bi.x, bj.x), iy1 = fmaxf(bi.y, bj.y);
            float ix2 = fminf(bi.z, bj.z), iy2 = fminf(bi.w, bj.w);
            float inter = fmaxf(ix2 - ix1, 0.0f) * fmaxf(iy2 - iy1, 0.0f);
            float areaj = fmaxf(bj.z - bj.x, 0.0f) * fmaxf(bj.w - bj.y, 0.0f);
            float uni = areai + areaj - inter;
            float iou = inter / fmaxf(uni, 1e-8f);
            if (iou > NMSTHR) bits |= 1ull << c;
        }
    }
    g_mask[(size_t)i * 64 + blockIdx.x] = bits;
}

// ---------------- kernel 6: 1-warp greedy scan + output ----------------
__global__ void k_scan(float* __restrict__ out, int out_size) {
    int lane = threadIdx.x;
    __shared__ int keep[MAXDET];
    int V = g_cnt[2]; if (V > KTOP) V = KTOP;
    // bitmap init: slots >= V are invalid (candidates sorted desc, valids first)
    int w0 = lane, w1 = lane + 32;
    int base0 = w0 * 64, base1 = w1 * 64;
    u64 r0 = (V <= base0) ? ~0ull : ((V >= base0 + 64) ? 0ull : ~((1ull << (V - base0)) - 1ull));
    u64 r1 = (V <= base1) ? ~0ull : ((V >= base1 + 64) ? 0ull : ~((1ull << (V - base1)) - 1ull));
    int cnt = 0;
    while (true) {
        u64 m0 = ~r0, m1 = ~r1;
        int c0 = m0 ? (base0 + (__ffsll((long long)m0) - 1)) : 0x7FFFFFFF;
        int c1 = m1 ? (base1 + (__ffsll((long long)m1) - 1)) : 0x7FFFFFFF;
        int c = (int)__reduce_min_sync(0xFFFFFFFFu, (u32)min(c0, c1));
        if (c == 0x7FFFFFFF) break;
        if (lane == 0) keep[cnt] = c;
        cnt++;
        if (cnt >= MAXDET) break;
        r0 |= g_mask[(size_t)c * 64 + lane];
        r1 |= g_mask[(size_t)c * 64 + 32 + lane];
        int w = c >> 6;
        u64 sb = 1ull << (c & 63);
        if (w == w0) r0 |= sb;
        else if (w == w1) r1 |= sb;
    }
    __syncwarp();
    for (int k = lane; k < out_size; k += 32) out[k] = 0.0f;
    __syncwarp();
    int nw = min(cnt, MAXDET);
    for (int s = lane; s < nw; s += 32) {
        int j = keep[s];
        float4 b = g_cbox[j];
        out[s * 4 + 0] = b.x;
        out[s * 4 + 1] = b.y;
        out[s * 4 + 2] = b.z;
        out[s * 4 + 3] = b.w;
        out[4 * MAXDET + s] = g_cscore[j];
        out[5 * MAXDET + s] = (float)g_ccls[j];
    }
    if (lane == 0) {
        if (out_size > 6 * MAXDET) out[6 * MAXDET] = (float)nw;
        g_cnt[2] = 0;                           // reset for next replay
    }
}

// ---------------- launcher ----------------
extern "C" void kernel_launch(void* const* d_in, const int* in_sizes, int n_in,
                              void* d_out, int out_size) {
    const float* reg = (const float*)d_in[1];
    const float* cls = (const float*)d_in[2];
    const float* anc = (const float*)d_in[3];
    int N = in_sizes[1] / 4;
    int C = (int)((long long)in_sizes[2] / N);
    int HW = in_sizes[0] / 3;
    int side = (int)(sqrt((double)HW) + 0.5);
    float Wm1 = (float)(side - 1);
    float Hm1 = (float)(side - 1);

    int prep_blocks = (N * 32 + 1023) / 1024;
    int pass_blocks = (N + 1023) / 1024;

    k_prep<<<prep_blocks, 1024>>>(reg, cls, anc, N, C, Wm1, Hm1, prep_blocks);
    k_hist2<<<pass_blocks, 1024>>>(N, pass_blocks);
    k_compact<<<pass_blocks, 1024>>>(N, pass_blocks);
    k_rank<<<KTOP / 16, 256>>>();
    k_mask<<<dim3(64, 16), 256>>>();
    k_scan<<<1, 32>>>((float*)d_out, out_size);
}

// round 7
// speedup vs baseline: 2.2071x; 1.0714x over previous
#include <cuda_runtime.h>
#include <stdint.h>
#include <math.h>

#define MAXN    131072
#define KTOP    4096
#define MAXDET  100
#define THRESH  0.5f
#define NMSTHR  0.5f

typedef unsigned long long u64;
typedef unsigned int u32;

// ---------------- static device scratch ----------------
__device__ float              g_score[MAXN];
__device__ u32                g_key[MAXN];
__device__ float4             g_box[MAXN];
__device__ int                g_cls[MAXN];
__device__ __align__(16) int  g_hist1[65536];
__device__ __align__(16) int  g_hist2[65536];
__device__ __align__(16) int  g_coarse1[1024];
__device__ __align__(16) int  g_coarse2[1024];
__device__ int                g_cnt[4];         // [0]=cnt_gt [1]=cnt_eq (prep zeroes) [2]=valid count (scan resets)
__device__ int                g_tick[4];
__device__ int                g_selinfo[2];
__device__ u32                g_Tkey;
__device__ int                g_G;
__device__ u64                g_sel[KTOP];
__device__ int                g_eq[KTOP];
__device__ float4             g_cbox[KTOP];
__device__ float              g_cscore[KTOP];
__device__ int                g_ccls[KTOP];
__device__ u64                g_mask[(size_t)KTOP * 64];   // lower-triangle words never written: stay 0

__device__ __forceinline__ u32 fkey(float f) {
    u32 u = __float_as_uint(f);
    return u ^ ((u >> 31) ? 0xFFFFFFFFu : 0x80000000u);
}
__device__ __forceinline__ float unfkey(u32 k) {
    u32 u = (k & 0x80000000u) ? (k ^ 0x80000000u) : ~k;
    return __uint_as_float(u);
}

// ------- block-wide radix find for 1024 threads -------
struct FindShared { int suf[1025]; int binres[2]; int h[64]; int hs[65]; int res[2]; };

__device__ void find_level1024(const int* __restrict__ coarse, const int* __restrict__ hist,
                               int base, FindShared& S, int& bucket, int& cntAbove) {
    int t = threadIdx.x;
    int seg = coarse[t];
    S.suf[t] = seg;
    __syncthreads();
    for (int off = 1; off < 1024; off <<= 1) {
        int v = (t + off < 1024) ? S.suf[t + off] : 0;
        __syncthreads();
        S.suf[t] += v;
        __syncthreads();
    }
    int exc = (t < 1023) ? S.suf[t + 1] : 0;
    int cg = exc + base;
    if (cg < KTOP && cg + seg >= KTOP) { S.binres[0] = t; S.binres[1] = cg; }
    __syncthreads();
    int bin = S.binres[0], bb = S.binres[1];
    if (t < 64) { int h = hist[bin * 64 + t]; S.h[t] = h; S.hs[t] = h; }
    __syncthreads();
    for (int off = 1; off < 64; off <<= 1) {
        int v = 0;
        if (t < 64) v = (t + off < 64) ? S.hs[t + off] : 0;
        __syncthreads();
        if (t < 64) S.hs[t] += v;
        __syncthreads();
    }
    if (t < 64) {
        int exc2 = (t < 63) ? S.hs[t + 1] : 0;
        int cg2 = exc2 + bb;
        if (cg2 < KTOP && cg2 + S.h[t] >= KTOP) { S.res[0] = bin * 64 + t; S.res[1] = cg2; }
    }
    __syncthreads();
    bucket = S.res[0];
    cntAbove = S.res[1];
}

// ---------------- kernel 1: argmax+decode+aggregated hist+valid count; last block finds B1 ----------------
__global__ __launch_bounds__(1024) void k_prep(const float* __restrict__ reg,
        const float* __restrict__ cls, const float* __restrict__ anc,
        int N, int C, float Wm1, float Hm1, int nblocks) {
    __shared__ u32 s_bucket[32];
    __shared__ FindShared FS;
    __shared__ int s_last;
    int tid = threadIdx.x;
    int gid = blockIdx.x * 1024 + tid;
    if (gid < 65536) g_hist2[gid] = 0;
    if (gid < 1024)  g_coarse2[gid] = 0;
    if (gid < 2)     g_cnt[gid] = 0;    // [2] is reset by k_scan

    int gw = gid >> 5;
    int lane = tid & 31;
    int warp = tid >> 5;
    u32 packed = 0xFFFFFFFFu;           // sentinel

    if (gw < N) {
        const float* row = cls + (size_t)gw * C;
        float bestv = -1e30f; int bc = 0x7FFFFFFF;
        for (int k = lane; k < C; k += 32) {
            float v = row[k];
            if (v > bestv) { bestv = v; bc = k; }
        }
        u32 mk = fkey(bestv);
        u32 m = __reduce_max_sync(0xFFFFFFFFu, mk);
        u32 cbc = (mk == m) ? (u32)bc : 0xFFFFFFFFu;
        u32 mbc = __reduce_min_sync(0xFFFFFFFFu, cbc);
        if (lane == 0) {
            float best = unfkey(m);
            float4 a = reinterpret_cast<const float4*>(anc)[gw];
            float4 r = reinterpret_cast<const float4*>(reg)[gw];
            float ya = (a.x + a.z) * 0.5f, xa = (a.y + a.w) * 0.5f;
            float ha = a.z - a.x, wa = a.w - a.y;
            float w = expf(r.w) * wa, h = expf(r.z) * ha;
            float yc = r.x * ha + ya, xc = r.y * wa + xa;
            g_box[gw] = make_float4(fmaxf(xc - w * 0.5f, 0.0f), fmaxf(yc - h * 0.5f, 0.0f),
                                    fminf(xc + w * 0.5f, Wm1),  fminf(yc + h * 0.5f, Hm1));
            bool valid = best > THRESH;
            float cand = valid ? best : -1.0f;
            g_score[gw] = cand;
            g_cls[gw] = (int)mbc;
            u32 k = fkey(cand);
            g_key[gw] = k;
            packed = (k >> 16) | (valid ? 0x10000u : 0u);
        }
    }
    if (lane == 0) s_bucket[warp] = packed;
    __syncthreads();
    if (tid < 32) {
        u32 raw = s_bucket[tid];
        bool present = raw != 0xFFFFFFFFu;
        u32 b = raw & 0xFFFFu;
        u32 vb = __ballot_sync(0xFFFFFFFFu, present && (raw & 0x10000u));
        if (tid == 0 && vb) atomicAdd(&g_cnt[2], __popc(vb));
        u32 mv = present ? b : 0xFFFFFFFFu;
        u32 mm = __match_any_sync(0xFFFFFFFFu, mv);
        if (present && tid == (__ffs(mm) - 1)) atomicAdd(&g_hist1[b], __popc(mm));
        u32 mv2 = present ? (b >> 6) : 0xFFFFFFFFu;
        u32 m2 = __match_any_sync(0xFFFFFFFFu, mv2);
        if (present && tid == (__ffs(m2) - 1)) atomicAdd(&g_coarse1[b >> 6], __popc(m2));
    }
    __threadfence();
    if (tid == 0) s_last = atomicAdd(&g_tick[0], 1);
    __syncthreads();
    if (s_last == nblocks - 1) {
        int B1, base1;
        find_level1024(g_coarse1, g_hist1, 0, FS, B1, base1);
        if (tid == 0) { g_selinfo[0] = B1; g_selinfo[1] = base1; g_tick[0] = 0; }
    }
}

// ---------------- kernel 2: level-2 histogram; last block finds Tkey/G ----------------
__global__ __launch_bounds__(1024) void k_hist2(int N, int nblocks) {
    __shared__ FindShared FS;
    __shared__ int s_last;
    int tid = threadIdx.x;
    int i = blockIdx.x * 1024 + tid;
    if (i < 65536) g_hist1[i] = 0;
    if (i < 1024)  g_coarse1[i] = 0;
    int B1 = g_selinfo[0];
    if (i < N) {
        u32 k = g_key[i];
        if ((int)(k >> 16) == B1) {
            atomicAdd(&g_hist2[k & 0xFFFFu], 1);
            atomicAdd(&g_coarse2[(k & 0xFFFFu) >> 6], 1);
        }
    }
    __threadfence();
    if (tid == 0) s_last = atomicAdd(&g_tick[1], 1);
    __syncthreads();
    if (s_last == nblocks - 1) {
        int B2, G;
        find_level1024(g_coarse2, g_hist2, g_selinfo[1], FS, B2, G);
        if (tid == 0) {
            g_Tkey = ((u32)g_selinfo[0] << 16) | (u32)B2;
            g_G = G;
            g_tick[1] = 0;
        }
    }
}

// ---------------- kernel 3: warp-aggregated compaction; last block fills equal-key slots ----------------
__global__ __launch_bounds__(1024) void k_compact(int N, int nblocks) {
    __shared__ int s_last;
    __shared__ int s_red[32];
    int tid = threadIdx.x;
    int lane = tid & 31;
    u32 lt = (1u << lane) - 1u;
    int i = blockIdx.x * 1024 + tid;
    if (i < 65536) g_hist2[i] = 0;
    if (i < 1024)  g_coarse2[i] = 0;
    u32 T = g_Tkey;
    u32 k = (i < N) ? g_key[i] : 0u;
    bool pgt = (i < N) && (k > T);
    bool peq = (i < N) && (k == T);
    u32 mgt = __ballot_sync(0xFFFFFFFFu, pgt);
    if (mgt) {
        int leader = __ffs(mgt) - 1;
        int base = 0;
        if (lane == leader) base = atomicAdd(&g_cnt[0], __popc(mgt));
        base = __shfl_sync(0xFFFFFFFFu, base, leader);
        if (pgt) g_sel[base + __popc(mgt & lt)] = ((u64)k << 32) | (u32)(~(u32)i);
    }
    u32 meq = __ballot_sync(0xFFFFFFFFu, peq);
    if (meq) {
        int leader = __ffs(meq) - 1;
        int base = 0;
        if (lane == leader) base = atomicAdd(&g_cnt[1], __popc(meq));
        base = __shfl_sync(0xFFFFFFFFu, base, leader);
        if (peq) {
            int p = base + __popc(meq & lt);
            if (p < KTOP) g_eq[p] = i;
        }
    }
    __threadfence();
    if (tid == 0) s_last = atomicAdd(&g_tick[2], 1);
    __syncthreads();
    if (s_last == nblocks - 1) {
        int G = g_G;
        int need = KTOP - G;
        int E = g_cnt[1]; if (E > KTOP) E = KTOP;
        for (int r = 0; r < need; r++) {
            int m = 0x7FFFFFFF;
            for (int j = tid; j < E; j += 1024) m = min(m, g_eq[j]);
            m = (int)__reduce_min_sync(0xFFFFFFFFu, (u32)m);
            if (lane == 0) s_red[tid >> 5] = m;
            __syncthreads();
            if (tid < 32) {
                int v = (int)__reduce_min_sync(0xFFFFFFFFu, (u32)s_red[tid]);
                if (tid == 0) s_red[0] = v;
            }
            __syncthreads();
            int minv = s_red[0];
            for (int j = tid; j < E; j += 1024) if (g_eq[j] == minv) g_eq[j] = 0x7FFFFFFF;
            if (tid == 0) g_sel[G + r] = ((u64)T << 32) | (u32)(~(u32)minv);
            __syncthreads();
        }
        if (tid == 0) g_tick[2] = 0;
    }
}

// ---------------- kernel 4: rank-by-count sort + gather (512 blocks, warp per candidate) ----------------
__global__ __launch_bounds__(256) void k_rank() {
    __shared__ u64 s[1024];                      // 8 KB tile
    int t = threadIdx.x;
    int lane = t & 31;
    int cand = blockIdx.x * 8 + (t >> 5);        // 8 warps, 1 candidate each
    u64 my = g_sel[cand];
    int r = 0;
    for (int tile = 0; tile < 4; tile++) {
        for (int j = t; j < 1024; j += 256) s[j] = g_sel[tile * 1024 + j];
        __syncthreads();
#pragma unroll 32
        for (int j = 0; j < 32; j++) r += (s[j * 32 + lane] > my);
        __syncthreads();
    }
    r = (int)__reduce_add_sync(0xFFFFFFFFu, (u32)r);
    if (lane == 0) {
        int idx = (int)(~(u32)my);
        g_cbox[r] = g_box[idx];
        g_cscore[r] = g_score[idx];
        g_ccls[r] = g_cls[idx];
    }
}

// ---------------- kernel 5: NMS bitmask, upper-triangle blocks only ----------------
__global__ __launch_bounds__(256) void k_mask() {
    if (blockIdx.x < 4 * blockIdx.y) return;
    __shared__ float4 cb[64];
    int t = threadIdx.x;
    int col0 = blockIdx.x * 64;
    int i = blockIdx.y * 256 + t;
    if (t < 64) cb[t] = g_cbox[col0 + t];
    __syncthreads();
    float4 bi = g_cbox[i];
    float areai = fmaxf(bi.z - bi.x, 0.0f) * fmaxf(bi.w - bi.y, 0.0f);
    u64 bits = 0;
#pragma unroll 4
    for (int c = 0; c < 64; c++) {
        int j = col0 + c;
        if (j > i) {
            float4 bj = cb[c];
            float ix1 = fmaxf(bi.x, bj.x), iy1 = fmaxf(bi.y, bj.y);
            float ix2 = fminf(bi.z, bj.z), iy2 = fminf(bi.w, bj.w);
            float inter = fmaxf(ix2 - ix1, 0.0f) * fmaxf(iy2 - iy1, 0.0f);
            float areaj = fmaxf(bj.z - bj.x, 0.0f) * fmaxf(bj.w - bj.y, 0.0f);
            float uni = areai + areaj - inter;
            float iou = inter / fmaxf(uni, 1e-8f);
            if (iou > NMSTHR) bits |= 1ull << c;
        }
    }
    g_mask[(size_t)i * 64 + blockIdx.x] = bits;
}

// ---------------- kernel 6: windowed greedy scan (1 warp) + output ----------------
// Window w covers sorted slots [w*64, w*64+64). All intra-window suppression bits
// for row i in the window live in the single word g_mask[i*64 + w], so each window
// resolves with one parallel load + a pure-ALU serial bit loop (exact greedy).
__global__ void k_scan(float* __restrict__ out, int out_size) {
    int lane = threadIdx.x;
    __shared__ int keep[MAXDET];
    __shared__ u64 s_iw[64];
    int V = g_cnt[2]; if (V > KTOP) V = KTOP;
    int base0 = lane * 64, base1 = (lane + 32) * 64;
    u64 r0 = (V <= base0) ? ~0ull : ((V >= base0 + 64) ? 0ull : ~((1ull << (V - base0)) - 1ull));
    u64 r1 = (V <= base1) ? ~0ull : ((V >= base1 + 64) ? 0ull : ~((1ull << (V - base1)) - 1ull));
    int cnt = 0;
    for (int w = 0; w < 64 && cnt < MAXDET; w++) {
        u64 rw = (w < 32) ? __shfl_sync(0xFFFFFFFFu, r0, w)
                          : __shfl_sync(0xFFFFFFFFu, r1, w - 32);
        if (rw == ~0ull) continue;               // window fully dead
        int W = w * 64;
        // stage intra-window suppression words (rows W..W+63, column-word w)
        s_iw[lane]      = g_mask[(size_t)(W + lane) * 64 + w];
        s_iw[lane + 32] = g_mask[(size_t)(W + 32 + lane) * 64 + w];
        __syncwarp();
        // serial exact-greedy resolve within the window (uniform across lanes)
        u64 removed = rw;
        u64 keptb = 0;
        for (int b = 0; b < 64; b++) {
            if (!((removed >> b) & 1ull)) {
                keptb |= 1ull << b;
                if (lane == 0) keep[cnt] = W + b;
                cnt++;
                if (cnt >= MAXDET) break;
                removed |= s_iw[b];
            }
        }
        if (cnt >= MAXDET) break;
        // apply kept rows' suppression to the global bitmap (batched independent loads)
        u64 kb = keptb;
        while (kb) {
            int b = __ffsll((long long)kb) - 1;
            kb &= kb - 1;
            r0 |= g_mask[(size_t)(W + b) * 64 + lane];
            r1 |= g_mask[(size_t)(W + b) * 64 + 32 + lane];
        }
        __syncwarp();
    }
    __syncwarp();
    for (int k = lane; k < out_size; k += 32) out[k] = 0.0f;
    __syncwarp();
    int nw = min(cnt, MAXDET);
    for (int s = lane; s < nw; s += 32) {
        int j = keep[s];
        float4 b = g_cbox[j];
        out[s * 4 + 0] = b.x;
        out[s * 4 + 1] = b.y;
        out[s * 4 + 2] = b.z;
        out[s * 4 + 3] = b.w;
        out[4 * MAXDET + s] = g_cscore[j];
        out[5 * MAXDET + s] = (float)g_ccls[j];
    }
    if (lane == 0) {
        if (out_size > 6 * MAXDET) out[6 * MAXDET] = (float)nw;
        g_cnt[2] = 0;                            // reset for next replay
    }
}

// ---------------- launcher ----------------
extern "C" void kernel_launch(void* const* d_in, const int* in_sizes, int n_in,
                              void* d_out, int out_size) {
    const float* reg = (const float*)d_in[1];
    const float* cls = (const float*)d_in[2];
    const float* anc = (const float*)d_in[3];
    int N = in_sizes[1] / 4;
    int C = (int)((long long)in_sizes[2] / N);
    int HW = in_sizes[0] / 3;
    int side = (int)(sqrt((double)HW) + 0.5);
    float Wm1 = (float)(side - 1);
    float Hm1 = (float)(side - 1);

    int prep_blocks = (N * 32 + 1023) / 1024;
    int pass_blocks = (N + 1023) / 1024;

    k_prep<<<prep_blocks, 1024>>>(reg, cls, anc, N, C, Wm1, Hm1, prep_blocks);
    k_hist2<<<pass_blocks, 1024>>>(N, pass_blocks);
    k_compact<<<pass_blocks, 1024>>>(N, pass_blocks);
    k_rank<<<KTOP / 8, 256>>>();
    k_mask<<<dim3(64, 16), 256>>>();
    k_scan<<<1, 32>>>((float*)d_out, out_size);
}